// round 10
// baseline (speedup 1.0000x reference)
#include <cuda_runtime.h>
#include <cuda_bf16.h>
#include <cstdint>
#include <math.h>

#define B_    16
#define CDIM  128
#define LSEQ  9216
#define DSTATE 2
#define DTRANK 8
#define OUTC  128
#define NPROJ 12
#define CHUNK 96
#define NCHUNK 96
#define LOG2E 1.4426950408889634f

// ---------------- device scratch ----------------
__device__ float g_xraw [(size_t)B_*LSEQ*CDIM];
__device__ float g_zsilu[(size_t)B_*LSEQ*CDIM];
__device__ float g_xi   [(size_t)B_*LSEQ*CDIM];
__device__ float g_dt   [(size_t)B_*LSEQ*CDIM];
__device__ float g_y    [(size_t)B_*LSEQ*CDIM];
__device__ float g_bc   [(size_t)B_*LSEQ*4];
__device__ float g_aggA [(size_t)B_*NCHUNK*CDIM*DSTATE];
__device__ float g_aggH [(size_t)B_*NCHUNK*CDIM*DSTATE];
__device__ float g_hinit[(size_t)B_*NCHUNK*CDIM*DSTATE];

__device__ __forceinline__ float silu_f(float v) {
    return __fdividef(v, 1.0f + __expf(-v));
}

__device__ __forceinline__ uint32_t smem_u32(const void* p) {
    uint32_t a;
    asm("{ .reg .u64 t; cvta.to.shared.u64 t, %1; cvt.u32.u64 %0, t; }" : "=r"(a) : "l"(p));
    return a;
}

#define LDMX4(r0,r1,r2,r3,addr) \
    asm volatile("ldmatrix.sync.aligned.m8n8.x4.shared.b16 {%0,%1,%2,%3}, [%4];" \
        : "=r"(r0),"=r"(r1),"=r"(r2),"=r"(r3) : "r"(addr))
#define MMA_BF16(D, A, B) \
    asm volatile("mma.sync.aligned.m16n8k16.row.col.f32.bf16.bf16.f32 " \
        "{%0,%1,%2,%3}, {%4,%5,%6,%7}, {%8,%9}, {%0,%1,%2,%3};" \
        : "+f"((D)[0]), "+f"((D)[1]), "+f"((D)[2]), "+f"((D)[3]) \
        : "r"((A)[0]), "r"((A)[1]), "r"((A)[2]), "r"((A)[3]), "r"((B)[0]), "r"((B)[1]))

__device__ __forceinline__ void split_pack(float4 v, uint2& hi, uint2& lo) {
    __nv_bfloat162 h0 = __floats2bfloat162_rn(v.x, v.y);
    __nv_bfloat162 h1 = __floats2bfloat162_rn(v.z, v.w);
    float r0 = v.x - __bfloat162float(h0.x);
    float r1 = v.y - __bfloat162float(h0.y);
    float r2 = v.z - __bfloat162float(h1.x);
    float r3 = v.w - __bfloat162float(h1.y);
    __nv_bfloat162 l0 = __floats2bfloat162_rn(r0, r1);
    __nv_bfloat162 l1 = __floats2bfloat162_rn(r2, r3);
    hi = make_uint2(*reinterpret_cast<uint32_t*>(&h0), *reinterpret_cast<uint32_t*>(&h1));
    lo = make_uint2(*reinterpret_cast<uint32_t*>(&l0), *reinterpret_cast<uint32_t*>(&l1));
}

// SMEM tile layout: bf16 [128 rows][128 k], row pitch 272 bytes (136 elem)
#define TPITCH_B 272u
#define TILE_B   (128u*TPITCH_B)     // 34816 bytes
#define OFF_AH   0u
#define OFF_AL   TILE_B
#define OFF_BH   (2u*TILE_B)
#define OFF_BL   (3u*TILE_B)
#define GEMM_SMEM (4u*TILE_B)        // 139264 bytes

// ---------------------------------------------------------------------------
// K1: in_proj via mma.sync bf16 hi/lo split.
// Per CTA: M = 128 e (half by blockIdx.y), N = 128 tokens, K = 128.
// A = Wi rows [e][k]; B = x tile [l][k] (transposed from x[b][k][l]).
// ---------------------------------------------------------------------------
__global__ __launch_bounds__(256)
void k_inproj_mma(const float* __restrict__ x, const float* __restrict__ Wi) {
    extern __shared__ __align__(16) char smraw[];
    const uint32_t sb = smem_u32(smraw);
    const int tid  = threadIdx.x;
    const int lane = tid & 31;
    const int wid  = tid >> 5;
    const int wm   = wid >> 2;          // 0..1  (e)
    const int wn   = wid & 3;           // 0..3  (l)
    const int b    = blockIdx.z;
    const int half = blockIdx.y;
    const int l0   = blockIdx.x * 128;

    // --- load + split Wi half: 128 e rows x 128 k ---
    for (int idx = tid; idx < 128 * 32; idx += 256) {
        int e = idx >> 5, k4 = (idx & 31) * 4;
        float4 w = *reinterpret_cast<const float4*>(&Wi[(size_t)(half*128 + e) * CDIM + k4]);
        uint2 hi, lo; split_pack(w, hi, lo);
        uint32_t off = e * TPITCH_B + k4 * 2;
        *reinterpret_cast<uint2*>(smraw + OFF_AH + off) = hi;
        *reinterpret_cast<uint2*>(smraw + OFF_AL + off) = lo;
    }
    // --- load + split + transpose x tile: [k][l] -> [l][k] ---
    {
        const float* xb = x + (size_t)b * CDIM * LSEQ;
        for (int idx = tid; idx < 128 * 32; idx += 256) {
            int k = idx >> 5, l4 = (idx & 31) * 4;
            float4 v = *reinterpret_cast<const float4*>(&xb[(size_t)k * LSEQ + l0 + l4]);
            float vv[4] = {v.x, v.y, v.z, v.w};
#pragma unroll
            for (int i = 0; i < 4; i++) {
                __nv_bfloat16 h = __float2bfloat16(vv[i]);
                __nv_bfloat16 l = __float2bfloat16(vv[i] - __bfloat162float(h));
                uint32_t off = (l4 + i) * TPITCH_B + k * 2;
                *reinterpret_cast<__nv_bfloat16*>(smraw + OFF_BH + off) = h;
                *reinterpret_cast<__nv_bfloat16*>(smraw + OFF_BL + off) = l;
            }
        }
    }
    __syncthreads();

    // ldmatrix lane addressing (both operands non-trans: smem rows = fragment rows)
    const uint32_t a_off = (uint32_t)((lane & 15) * TPITCH_B + ((lane >> 4) * 8) * 2);
    const uint32_t b_off = (uint32_t)((((lane >> 4) & 1) * 8 + (lane & 7)) * TPITCH_B
                                      + (((lane >> 3) & 1) * 8) * 2);

    float d[4][4][4];
#pragma unroll
    for (int i = 0; i < 4; i++)
#pragma unroll
        for (int j = 0; j < 4; j++)
#pragma unroll
            for (int q = 0; q < 4; q++) d[i][j][q] = 0.f;

#pragma unroll 1
    for (int ks = 0; ks < 8; ks++) {
        const uint32_t kb = ks * 32;    // 16 k * 2 bytes
        uint32_t ah[4][4], al[4][4], bh[4][2], bl[4][2];
#pragma unroll
        for (int mf = 0; mf < 4; mf++) {
            uint32_t off = (wm*64 + mf*16) * TPITCH_B + kb + a_off;
            LDMX4(ah[mf][0], ah[mf][1], ah[mf][2], ah[mf][3], sb + OFF_AH + off);
            LDMX4(al[mf][0], al[mf][1], al[mf][2], al[mf][3], sb + OFF_AL + off);
        }
#pragma unroll
        for (int p = 0; p < 2; p++) {
            uint32_t off = (wn*32 + p*16) * TPITCH_B + kb + b_off;
            LDMX4(bh[2*p][0], bh[2*p][1], bh[2*p+1][0], bh[2*p+1][1], sb + OFF_BH + off);
            LDMX4(bl[2*p][0], bl[2*p][1], bl[2*p+1][0], bl[2*p+1][1], sb + OFF_BL + off);
        }
#pragma unroll
        for (int mf = 0; mf < 4; mf++)
#pragma unroll
            for (int nf = 0; nf < 4; nf++) {
                MMA_BF16(d[mf][nf], ah[mf], bh[nf]);
                MMA_BF16(d[mf][nf], ah[mf], bl[nf]);
                MMA_BF16(d[mf][nf], al[mf], bh[nf]);
            }
    }
    __syncthreads();

    // --- stage D[e][l] into f32 tile (pitch 129), then coalesced write ---
    float* tile = reinterpret_cast<float*>(smraw);   // [128][129]
#pragma unroll
    for (int mf = 0; mf < 4; mf++)
#pragma unroll
        for (int nf = 0; nf < 4; nf++) {
            int row = wm*64 + mf*16 + (lane >> 2);
            int col = wn*32 + nf*8 + (lane & 3) * 2;
            tile[ row      * 129 + col    ] = d[mf][nf][0];
            tile[ row      * 129 + col + 1] = d[mf][nf][1];
            tile[(row + 8) * 129 + col    ] = d[mf][nf][2];
            tile[(row + 8) * 129 + col + 1] = d[mf][nf][3];
        }
    __syncthreads();

    float* dst = (half == 0 ? g_xraw : g_zsilu);
    for (int idx = tid; idx < 128 * 32; idx += 256) {
        int l = idx >> 5, e4 = (idx & 31) * 4;
        float4 v;
        v.x = tile[(e4+0)*129 + l];
        v.y = tile[(e4+1)*129 + l];
        v.z = tile[(e4+2)*129 + l];
        v.w = tile[(e4+3)*129 + l];
        if (half == 1) { v.x = silu_f(v.x); v.y = silu_f(v.y); v.z = silu_f(v.z); v.w = silu_f(v.w); }
        *reinterpret_cast<float4*>(&dst[((size_t)b * LSEQ + l0 + l) * CDIM + e4]) = v;
    }
}

// ---------------------------------------------------------------------------
// K2: phaseA — 256 threads. conv+silu -> xi, x_dbl -> bc, dt, chunk aggregates.
// ---------------------------------------------------------------------------
#define SM2_FLOATS (96*132 + 12*132 + 96*16)

__global__ __launch_bounds__(256)
void k_phaseA(const float* __restrict__ conv_w, const float* __restrict__ conv_b,
              const float* __restrict__ x_proj_w, const float* __restrict__ dt_proj_w,
              const float* __restrict__ dt_proj_b, const float* __restrict__ A_log) {
    extern __shared__ float sm[];
    float* xi_s = sm;
    float* xw_s = sm + 96*132;
    float* xd_s = xw_s + 12*132;

    const int ch = blockIdx.x;
    const int b  = blockIdx.y;
    const int l0 = ch * CHUNK;
    const int tid = threadIdx.x;
    const int d    = tid & 127;
    const int half = tid >> 7;

    for (int i = tid; i < NPROJ*CDIM; i += 256)
        xw_s[(i >> 7)*132 + (i & 127)] = x_proj_w[i];

    {
        const float cw0 = conv_w[d*4+0], cw1 = conv_w[d*4+1];
        const float cw2 = conv_w[d*4+2], cw3 = conv_w[d*4+3];
        const float cb  = conv_b[d];
        const float* xr = g_xraw + (size_t)b * LSEQ * CDIM;
        float* xo = g_xi + ((size_t)b * LSEQ + l0) * CDIM + d;
        const int ls = half * 48;
        const int la0 = l0 + ls;
        float p0 = (la0 >= 3) ? xr[(size_t)(la0-3)*CDIM + d] : 0.f;
        float p1 = (la0 >= 2) ? xr[(size_t)(la0-2)*CDIM + d] : 0.f;
        float p2 = (la0 >= 1) ? xr[(size_t)(la0-1)*CDIM + d] : 0.f;
#pragma unroll 4
        for (int l = ls; l < ls + 48; l++) {
            float c = xr[(size_t)(l0+l)*CDIM + d];
            float a = fmaf(cw0,p0, fmaf(cw1,p1, fmaf(cw2,p2, fmaf(cw3,c, cb))));
            float v = silu_f(a);
            xi_s[l*132 + d] = v;
            xo[(size_t)l*CDIM] = v;
            p0 = p1; p1 = p2; p2 = c;
        }
    }
    __syncthreads();

    {
        float* bco = g_bc + ((size_t)b * LSEQ + l0) * 4;
        for (int p = tid; p < CHUNK*NPROJ; p += 256) {
            int l = p / 12, j = p - l*12;
            const float4* xr4 = reinterpret_cast<const float4*>(&xi_s[l*132]);
            const float4* wr4 = reinterpret_cast<const float4*>(&xw_s[j*132]);
            float s = 0.f;
#pragma unroll
            for (int k = 0; k < 32; k++) {
                float4 xa = xr4[k], wa = wr4[k];
                s = fmaf(xa.x, wa.x, s); s = fmaf(xa.y, wa.y, s);
                s = fmaf(xa.z, wa.z, s); s = fmaf(xa.w, wa.w, s);
            }
            xd_s[l*16 + j] = s;
            if (j >= 8) bco[l*4 + (j-8)] = s;
        }
    }
    __syncthreads();

    if (tid < 128) {
        float wdt[DTRANK];
#pragma unroll
        for (int r = 0; r < DTRANK; r++) wdt[r] = dt_proj_w[d*DTRANK + r];
        const float bdt = dt_proj_b[d];
        const float a0L = -__expf(A_log[2*d+0]) * LOG2E;
        const float a1L = -__expf(A_log[2*d+1]) * LOG2E;
        float* dto = g_dt + ((size_t)b * LSEQ + l0) * CDIM + d;

        float h0 = 0.f, h1 = 0.f, sdt = 0.f;
#pragma unroll 2
        for (int l = 0; l < CHUNK; l++) {
            const float* xd = &xd_s[l*16];
            float t = bdt;
#pragma unroll
            for (int r = 0; r < DTRANK; r++) t = fmaf(xd[r], wdt[r], t);
            float ex = __expf(t);
            float dt = (t > 20.f) ? t : __logf(1.f + ex);
            dto[(size_t)l*CDIM] = dt;
            sdt += dt;
            float e0 = exp2f(dt * a0L);
            float e1 = exp2f(dt * a1L);
            float dbx = dt * xi_s[l*132 + d];
            h0 = fmaf(e0, h0, dbx * xd[8]);
            h1 = fmaf(e1, h1, dbx * xd[9]);
        }
        const size_t base = (((size_t)b*NCHUNK + ch)*CDIM + d)*DSTATE;
        g_aggA[base+0] = exp2f(a0L * sdt);
        g_aggA[base+1] = exp2f(a1L * sdt);
        g_aggH[base+0] = h0;
        g_aggH[base+1] = h1;
    }
}

// ---------------------------------------------------------------------------
// K3: chain chunk aggregates
// ---------------------------------------------------------------------------
__global__ __launch_bounds__(256)
void k_combine() {
    const int g = blockIdx.x * blockDim.x + threadIdx.x;
    const int b = g >> 8;
    const int rem = g & 255;
    float h = 0.f;
    for (int ch = 0; ch < NCHUNK; ch++) {
        const size_t idx = (((size_t)b*NCHUNK + ch) * CDIM * DSTATE) + rem;
        g_hinit[idx] = h;
        h = fmaf(g_aggA[idx], h, g_aggH[idx]);
    }
}

// ---------------------------------------------------------------------------
// K4: scan
// ---------------------------------------------------------------------------
__global__ __launch_bounds__(128)
void k_scan(const float* __restrict__ A_log, const float* __restrict__ D_param) {
    __shared__ float bc_s[CHUNK*4];
    const int ch = blockIdx.x;
    const int b  = blockIdx.y;
    const int l0 = ch * CHUNK;
    const int d  = threadIdx.x;

    {
        const float* bcg = g_bc + ((size_t)b * LSEQ + l0) * 4;
        for (int i = d; i < CHUNK*4; i += 128) bc_s[i] = bcg[i];
    }
    const float a0L = -__expf(A_log[2*d+0]) * LOG2E;
    const float a1L = -__expf(A_log[2*d+1]) * LOG2E;
    const float Dp  = D_param[d];
    const size_t base = (((size_t)b*NCHUNK + ch)*CDIM + d)*DSTATE;
    float h0 = g_hinit[base+0];
    float h1 = g_hinit[base+1];

    const size_t off = ((size_t)b * LSEQ + l0) * CDIM + d;
    const float* dtp = g_dt    + off;
    const float* xip = g_xi    + off;
    const float* zp  = g_zsilu + off;
    float*       yp  = g_y     + off;
    __syncthreads();

#pragma unroll 4
    for (int l = 0; l < CHUNK; l++) {
        float dt = dtp[(size_t)l*CDIM];
        float xi = xip[(size_t)l*CDIM];
        float zv = zp [(size_t)l*CDIM];
        float e0 = exp2f(dt * a0L);
        float e1 = exp2f(dt * a1L);
        float dbx = dt * xi;
        h0 = fmaf(e0, h0, dbx * bc_s[l*4+0]);
        h1 = fmaf(e1, h1, dbx * bc_s[l*4+1]);
        float y = fmaf(h0, bc_s[l*4+2], fmaf(h1, bc_s[l*4+3], Dp * xi));
        yp[(size_t)l*CDIM] = y * zv;
    }
}

// ---------------------------------------------------------------------------
// K5: out_proj via mma.sync bf16 hi/lo split + fused LayerNorm.
// Per CTA: M = 128 o, N = 128 tokens, K = 128.
// ---------------------------------------------------------------------------
__global__ __launch_bounds__(256)
void k_outproj_mma(const float* __restrict__ Wout, const float* __restrict__ gamma,
                   const float* __restrict__ beta, float* __restrict__ out) {
    extern __shared__ __align__(16) char smraw[];
    const uint32_t sb = smem_u32(smraw);
    const int tid  = threadIdx.x;
    const int lane = tid & 31;
    const int wid  = tid >> 5;
    const int wm   = wid >> 2;
    const int wn   = wid & 3;
    const int b    = blockIdx.y;
    const int l0   = blockIdx.x * 128;

    for (int idx = tid; idx < 128 * 32; idx += 256) {
        int o = idx >> 5, k4 = (idx & 31) * 4;
        float4 w = *reinterpret_cast<const float4*>(&Wout[(size_t)o * CDIM + k4]);
        uint2 hi, lo; split_pack(w, hi, lo);
        uint32_t off = o * TPITCH_B + k4 * 2;
        *reinterpret_cast<uint2*>(smraw + OFF_AH + off) = hi;
        *reinterpret_cast<uint2*>(smraw + OFF_AL + off) = lo;
    }
    {
        const float* yb = g_y + ((size_t)b * LSEQ + l0) * CDIM;
        for (int idx = tid; idx < 128 * 32; idx += 256) {
            int l = idx >> 5, k4 = (idx & 31) * 4;
            float4 v = *reinterpret_cast<const float4*>(&yb[(size_t)l * CDIM + k4]);
            uint2 hi, lo; split_pack(v, hi, lo);
            uint32_t off = l * TPITCH_B + k4 * 2;
            *reinterpret_cast<uint2*>(smraw + OFF_BH + off) = hi;
            *reinterpret_cast<uint2*>(smraw + OFF_BL + off) = lo;
        }
    }
    __syncthreads();

    const uint32_t a_off = (uint32_t)((lane & 15) * TPITCH_B + ((lane >> 4) * 8) * 2);
    const uint32_t b_off = (uint32_t)((((lane >> 4) & 1) * 8 + (lane & 7)) * TPITCH_B
                                      + (((lane >> 3) & 1) * 8) * 2);

    float d[4][4][4];
#pragma unroll
    for (int i = 0; i < 4; i++)
#pragma unroll
        for (int j = 0; j < 4; j++)
#pragma unroll
            for (int q = 0; q < 4; q++) d[i][j][q] = 0.f;

#pragma unroll 1
    for (int ks = 0; ks < 8; ks++) {
        const uint32_t kb = ks * 32;
        uint32_t ah[4][4], al[4][4], bh[4][2], bl[4][2];
#pragma unroll
        for (int mf = 0; mf < 4; mf++) {
            uint32_t off = (wm*64 + mf*16) * TPITCH_B + kb + a_off;
            LDMX4(ah[mf][0], ah[mf][1], ah[mf][2], ah[mf][3], sb + OFF_AH + off);
            LDMX4(al[mf][0], al[mf][1], al[mf][2], al[mf][3], sb + OFF_AL + off);
        }
#pragma unroll
        for (int p = 0; p < 2; p++) {
            uint32_t off = (wn*32 + p*16) * TPITCH_B + kb + b_off;
            LDMX4(bh[2*p][0], bh[2*p][1], bh[2*p+1][0], bh[2*p+1][1], sb + OFF_BH + off);
            LDMX4(bl[2*p][0], bl[2*p][1], bl[2*p+1][0], bl[2*p+1][1], sb + OFF_BL + off);
        }
#pragma unroll
        for (int mf = 0; mf < 4; mf++)
#pragma unroll
            for (int nf = 0; nf < 4; nf++) {
                MMA_BF16(d[mf][nf], ah[mf], bh[nf]);
                MMA_BF16(d[mf][nf], ah[mf], bl[nf]);
                MMA_BF16(d[mf][nf], al[mf], bh[nf]);
            }
    }
    __syncthreads();

    // stage D[o][l] (pitch 129), LN over o per token, coalesced write
    float* tile = reinterpret_cast<float*>(smraw);   // [128][129]
    float* mu_s = tile + 128*129;
    float* rs_s = mu_s + 128;
#pragma unroll
    for (int mf = 0; mf < 4; mf++)
#pragma unroll
        for (int nf = 0; nf < 4; nf++) {
            int row = wm*64 + mf*16 + (lane >> 2);
            int col = wn*32 + nf*8 + (lane & 3) * 2;
            tile[ row      * 129 + col    ] = d[mf][nf][0];
            tile[ row      * 129 + col + 1] = d[mf][nf][1];
            tile[(row + 8) * 129 + col    ] = d[mf][nf][2];
            tile[(row + 8) * 129 + col + 1] = d[mf][nf][3];
        }
    __syncthreads();

    if (tid < 128) {
        float s = 0.f, q = 0.f;
#pragma unroll 8
        for (int o = 0; o < 128; o++) {
            float v = tile[o*129 + tid];
            s += v;
            q = fmaf(v, v, q);
        }
        float mu = s * (1.0f/128.0f);
        float var = q * (1.0f/128.0f) - mu*mu;
        mu_s[tid] = mu;
        rs_s[tid] = rsqrtf(var + 1e-5f);
    }
    __syncthreads();

    for (int p = tid; p < 128*32; p += 256) {
        int o  = p >> 5;
        int l4 = (p & 31) * 4;
        float g  = gamma[o];
        float bt = beta[o];
        float4 v;
        v.x = fmaf((tile[o*129 + l4+0] - mu_s[l4+0]) * rs_s[l4+0], g, bt);
        v.y = fmaf((tile[o*129 + l4+1] - mu_s[l4+1]) * rs_s[l4+1], g, bt);
        v.z = fmaf((tile[o*129 + l4+2] - mu_s[l4+2]) * rs_s[l4+2], g, bt);
        v.w = fmaf((tile[o*129 + l4+3] - mu_s[l4+3]) * rs_s[l4+3], g, bt);
        *reinterpret_cast<float4*>(&out[((size_t)(b*OUTC + o))*LSEQ + l0 + l4]) = v;
    }
}

// ---------------------------------------------------------------------------
extern "C" void kernel_launch(void* const* d_in, const int* in_sizes, int n_in,
                              void* d_out, int out_size) {
    const float* x          = (const float*)d_in[0];
    const float* in_proj_w  = (const float*)d_in[1];
    const float* conv_w     = (const float*)d_in[2];
    const float* conv_b     = (const float*)d_in[3];
    const float* x_proj_w   = (const float*)d_in[4];
    const float* dt_proj_w  = (const float*)d_in[5];
    const float* dt_proj_b  = (const float*)d_in[6];
    const float* A_log      = (const float*)d_in[7];
    const float* D_param    = (const float*)d_in[8];
    const float* out_proj_w = (const float*)d_in[9];
    const float* ln_gamma   = (const float*)d_in[10];
    const float* ln_beta    = (const float*)d_in[11];
    float* out = (float*)d_out;

    const int sm2 = SM2_FLOATS * sizeof(float);
    cudaFuncSetAttribute(k_inproj_mma,  cudaFuncAttributeMaxDynamicSharedMemorySize, (int)GEMM_SMEM);
    cudaFuncSetAttribute(k_phaseA,      cudaFuncAttributeMaxDynamicSharedMemorySize, sm2);
    cudaFuncSetAttribute(k_outproj_mma, cudaFuncAttributeMaxDynamicSharedMemorySize, (int)GEMM_SMEM);

    k_inproj_mma <<<dim3(LSEQ/128, 2, B_), 256, GEMM_SMEM>>>(x, in_proj_w);
    k_phaseA     <<<dim3(NCHUNK, B_), 256, sm2>>>(conv_w, conv_b, x_proj_w,
                                                  dt_proj_w, dt_proj_b, A_log);
    k_combine    <<<16, 256>>>();
    k_scan       <<<dim3(NCHUNK, B_), 128>>>(A_log, D_param);
    k_outproj_mma<<<dim3(LSEQ/128, B_), 256, GEMM_SMEM>>>(out_proj_w, ln_gamma, ln_beta, out);
}